// round 3
// baseline (speedup 1.0000x reference)
#include <cuda_runtime.h>
#include <cstdint>

// Problem constants
#define NPOS 131072
#define CCH  128
#define TN   64              // output rows per CTA
#define ROWS (TN + 4)        // h rows incl. halo 2 each side
#define NTHREADS 512

// ---------------------------------------------------------------------------
// Persistent scratch (device globals are the allowed scratch mechanism)
// Transposed weights: Wt[i][o] so GEMMs read 4 consecutive o per thread (LDS.128)
// ---------------------------------------------------------------------------
__device__ __align__(16) float g_Wt1[128 * 128];      // b1 pointwise
__device__ __align__(16) float g_Wt2[128 * 128];      // b2 1x1
__device__ __align__(16) float g_Wt5[128 * 128];      // b2 pointwise
__device__ __align__(16) float g_WtF[2 * 128 * 128];  // fusion: [0]=h half, [1]=b2 half
__device__ float g_dw1[3 * 128];                      // b1 depthwise taps (middle column)
__device__ float g_dw2[3 * 128];                      // b2 depthwise taps

// ---------------------------------------------------------------------------
// Prep: transpose weights, extract effective 3-tap depthwise kernels.
// (3x3 conv on a width-1 image with padding 1 only ever uses kw==1.)
// ---------------------------------------------------------------------------
__global__ void prep_kernel(const float* __restrict__ w1dw, const float* __restrict__ w1pw,
                            const float* __restrict__ w21,  const float* __restrict__ w2dw,
                            const float* __restrict__ w2pw, const float* __restrict__ wf)
{
    int t = blockIdx.x * blockDim.x + threadIdx.x;
    if (t < 128 * 128) {
        int i = t >> 7, o = t & 127;
        g_Wt1[t] = w1pw[o * 128 + i];
        g_Wt2[t] = w21 [o * 128 + i];
        g_Wt5[t] = w2pw[o * 128 + i];
        g_WtF[t]             = wf[o * 256 + i];         // channels 0..127  (h)
        g_WtF[128 * 128 + t] = wf[o * 256 + 128 + i];   // channels 128..255 (b2)
    }
    if (t < 128) {
#pragma unroll
        for (int k = 0; k < 3; k++) {
            g_dw1[k * 128 + t] = w1dw[t * 9 + k * 3 + 1];
            g_dw2[k * 128 + t] = w2dw[t * 9 + k * 3 + 1];
        }
    }
}

// ---------------------------------------------------------------------------
// JAX threefry2x32, key = PRNGKey(42) = (0, 42), partitionable random_bits:
// element j -> (b1,b2) = threefry2x32(key, (j>>32, j&0xffffffff)); for
// bit_width 32 the value is b1 ^ b2 (XOR of both output words — see
// _threefry_random_bits_partitionable). keep prob 0.5: uniform < 0.5
// <=> bits < 2^31 <=> (int)bits >= 0.
// ---------------------------------------------------------------------------
__device__ __forceinline__ unsigned tf_bits(unsigned x1)
{
    unsigned x0 = 0u;
    const unsigned k0 = 0u, k1 = 42u;
    const unsigned k2 = 0x1BD11BDAu ^ k0 ^ k1;
#define TF_R(r) { x0 += x1; x1 = __funnelshift_l(x1, x1, (r)); x1 ^= x0; }
    x0 += k0; x1 += k1;
    TF_R(13) TF_R(15) TF_R(26) TF_R(6)
    x0 += k1; x1 += k2 + 1u;
    TF_R(17) TF_R(29) TF_R(16) TF_R(24)
    x0 += k2; x1 += k0 + 2u;
    TF_R(13) TF_R(15) TF_R(26) TF_R(6)
    x0 += k0; x1 += k1 + 3u;
    TF_R(17) TF_R(29) TF_R(16) TF_R(24)
    x0 += k1; x1 += k2 + 4u;
    TF_R(13) TF_R(15) TF_R(26) TF_R(6)
    x0 += k2; x1 += k0 + 5u;
#undef TF_R
    return x0 ^ x1;  // XOR of both threefry output words (32-bit partitionable path)
}

// ---------------------------------------------------------------------------
// Register-tiled 128-ch pointwise GEMM stage out of shared memory.
//   Y[row][o] = relu( sum_i V[row][i] * W[i][o] )           (MODE 0)
//   MODE 1 additionally: += ADD[row][o]; apply threefry mask; zero rows whose
//   global n is outside [0, NPOS) (reference zero-pads b2, not recomputes it).
// Thread map: 512 thr = 32 o-groups (4 consecutive o -> LDS.128, conflict-free)
//             x 16 row-groups (4 rows, V reads are warp-broadcasts).
// ---------------------------------------------------------------------------
template <int MODE>
__device__ __forceinline__ void gemm128(const float* __restrict__ V,
                                        const float* __restrict__ W,
                                        float* __restrict__ Y,
                                        const float* __restrict__ ADD,
                                        int rlo, int rhi, int tid, int g0)
{
    const int o0 = (tid & 31) << 2;
    const int ng = tid >> 5;
    for (int base = rlo; base < rhi; base += 64) {
        const int r0 = base + (ng << 2);
        if (r0 >= rhi) continue;                 // tail pass: idle row-groups skip (no syncs inside)
        const float* Vp[4];
#pragma unroll
        for (int j = 0; j < 4; j++) {
            int rr = r0 + j;
            if (rr > rhi - 1) rr = rhi - 1;      // clamp: duplicate reads, stores guarded below
            Vp[j] = V + rr * 128;
        }
        float acc[4][4];
#pragma unroll
        for (int a = 0; a < 4; a++)
#pragma unroll
            for (int b = 0; b < 4; b++) acc[a][b] = 0.f;

#pragma unroll 4
        for (int i = 0; i < 128; i++) {
            const float4 w4 = *(const float4*)(W + i * 128 + o0);
#pragma unroll
            for (int j = 0; j < 4; j++) {
                const float v = Vp[j][i];
                acc[j][0] += v * w4.x;
                acc[j][1] += v * w4.y;
                acc[j][2] += v * w4.z;
                acc[j][3] += v * w4.w;
            }
        }
#pragma unroll
        for (int j = 0; j < 4; j++) {
            const int row = r0 + j;
            if (row >= rhi) break;
            float4 res;
            res.x = fmaxf(acc[j][0], 0.f);
            res.y = fmaxf(acc[j][1], 0.f);
            res.z = fmaxf(acc[j][2], 0.f);
            res.w = fmaxf(acc[j][3], 0.f);
            if (MODE == 1) {
                const int n = g0 - 2 + row;
                const float4 ad = *(const float4*)(ADD + row * 128 + o0);
                res.x += ad.x; res.y += ad.y; res.z += ad.z; res.w += ad.w;
                if ((unsigned)n >= (unsigned)NPOS) {
                    res.x = res.y = res.z = res.w = 0.f;   // halo outside tensor: b2 is zero-padded
                } else {
                    // mask flat index over shape (1, C, N, 1): j = c*N + n
                    const unsigned jb = (unsigned)o0 * (unsigned)NPOS + (unsigned)n;
                    if ((int)tf_bits(jb + 0u * NPOS) < 0) res.x = 0.f;
                    if ((int)tf_bits(jb + 1u * NPOS) < 0) res.y = 0.f;
                    if ((int)tf_bits(jb + 2u * NPOS) < 0) res.z = 0.f;
                    if ((int)tf_bits(jb + 3u * NPOS) < 0) res.w = 0.f;
                }
            }
            *(float4*)(Y + row * 128 + o0) = res;
        }
    }
}

__device__ __forceinline__ void load_w(float* __restrict__ dst, const float* __restrict__ src, int tid)
{
    const float4* s = (const float4*)src;
    float4* d = (float4*)dst;
#pragma unroll
    for (int i = 0; i < 8; i++) d[tid + i * NTHREADS] = s[tid + i * NTHREADS];
}

// ---------------------------------------------------------------------------
// Fully fused block kernel. One CTA = TN output rows; halo 2.
// Buffers: sh_h (input rows), sh_a / sh_b ping-pong, sh_w (one 64KB weight).
// ---------------------------------------------------------------------------
__global__ void __launch_bounds__(NTHREADS, 1)
fused_kernel(const float* __restrict__ x, float* __restrict__ out)
{
    extern __shared__ float smem[];
    float* sh_h = smem;                      // ROWS*128
    float* sh_a = smem + ROWS * 128;         // ROWS*128
    float* sh_b = smem + 2 * ROWS * 128;     // ROWS*128
    float* sh_w = smem + 3 * ROWS * 128;     // 128*128

    const int tid = threadIdx.x;
    const int g0  = blockIdx.x * TN;

    // ---- load h rows [g0-2, g0+TN+2), zero-padded ----
    for (int idx = tid; idx < ROWS * 32; idx += NTHREADS) {
        const int l = idx >> 5;
        const int n = g0 - 2 + l;
        float4 v = make_float4(0.f, 0.f, 0.f, 0.f);
        if ((unsigned)n < (unsigned)NPOS) v = ((const float4*)x)[n * 32 + (idx & 31)];
        ((float4*)sh_h)[idx] = v;
    }
    __syncthreads();

    // ---- stage A: b1_dw = relu(3-tap conv(h)), rows [1, TN+3) ----
    {
        const int c = tid & 127;
        const float t0 = g_dw1[c], t1 = g_dw1[128 + c], t2 = g_dw1[256 + c];
        for (int l = 1 + (tid >> 7); l < TN + 3; l += 4) {
            float v = t0 * sh_h[(l - 1) * 128 + c] + t1 * sh_h[l * 128 + c] + t2 * sh_h[(l + 1) * 128 + c];
            sh_a[l * 128 + c] = fmaxf(v, 0.f);
        }
    }
    __syncthreads();

    // ---- stage B: b1 = relu(W1 . b1_dw) -> sh_b ----
    load_w(sh_w, g_Wt1, tid);
    __syncthreads();
    gemm128<0>(sh_a, sh_w, sh_b, nullptr, 1, TN + 3, tid, g0);
    __syncthreads();

    // ---- stage C: b2 = mask * (relu(W2 . h) + b1) -> sh_a ----
    load_w(sh_w, g_Wt2, tid);
    __syncthreads();
    gemm128<1>(sh_h, sh_w, sh_a, sh_b, 1, TN + 3, tid, g0);
    __syncthreads();

    // ---- stage D: t = relu(3-tap conv(b2)), rows [2, TN+2) -> sh_b ----
    {
        const int c = tid & 127;
        const float t0 = g_dw2[c], t1 = g_dw2[128 + c], t2 = g_dw2[256 + c];
        for (int l = 2 + (tid >> 7); l < TN + 2; l += 4) {
            float v = t0 * sh_a[(l - 1) * 128 + c] + t1 * sh_a[l * 128 + c] + t2 * sh_a[(l + 1) * 128 + c];
            sh_b[l * 128 + c] = fmaxf(v, 0.f);
        }
    }
    __syncthreads();

    // ---- stage E: u = relu(W5 . t) -> sh_a ----
    load_w(sh_w, g_Wt5, tid);
    __syncthreads();
    gemm128<0>(sh_b, sh_w, sh_a, nullptr, 2, TN + 2, tid, g0);
    __syncthreads();

    // ---- stage F: out = relu(WF_h . h + WF_b . u), rows [2, TN+2) exactly 64 ----
    load_w(sh_w, g_WtF, tid);
    __syncthreads();
    {
        const int o0 = (tid & 31) << 2;
        const int r0 = 2 + ((tid >> 5) << 2);   // 2..62, rows r0..r0+3 all valid
        float acc[4][4];
#pragma unroll
        for (int a = 0; a < 4; a++)
#pragma unroll
            for (int b = 0; b < 4; b++) acc[a][b] = 0.f;

        const float* Vp0 = sh_h + r0 * 128;
#pragma unroll 4
        for (int i = 0; i < 128; i++) {
            const float4 w4 = *(const float4*)(sh_w + i * 128 + o0);
#pragma unroll
            for (int j = 0; j < 4; j++) {
                const float v = Vp0[j * 128 + i];
                acc[j][0] += v * w4.x; acc[j][1] += v * w4.y;
                acc[j][2] += v * w4.z; acc[j][3] += v * w4.w;
            }
        }
        __syncthreads();
        load_w(sh_w, g_WtF + 128 * 128, tid);
        __syncthreads();
        const float* Vp1 = sh_a + r0 * 128;
#pragma unroll 4
        for (int i = 0; i < 128; i++) {
            const float4 w4 = *(const float4*)(sh_w + i * 128 + o0);
#pragma unroll
            for (int j = 0; j < 4; j++) {
                const float v = Vp1[j * 128 + i];
                acc[j][0] += v * w4.x; acc[j][1] += v * w4.y;
                acc[j][2] += v * w4.z; acc[j][3] += v * w4.w;
            }
        }
#pragma unroll
        for (int j = 0; j < 4; j++) {
            const int n = g0 - 2 + r0 + j;      // in [g0, g0+TN)
            float4 res;
            res.x = fmaxf(acc[j][0], 0.f);
            res.y = fmaxf(acc[j][1], 0.f);
            res.z = fmaxf(acc[j][2], 0.f);
            res.w = fmaxf(acc[j][3], 0.f);
            *(float4*)(out + n * 128 + o0) = res;
        }
    }
}

// ---------------------------------------------------------------------------
extern "C" void kernel_launch(void* const* d_in, const int* in_sizes, int n_in,
                              void* d_out, int out_size)
{
    const float* x    = (const float*)d_in[0];
    const float* w1dw = (const float*)d_in[1];
    const float* w1pw = (const float*)d_in[2];
    const float* w21  = (const float*)d_in[3];
    const float* w2dw = (const float*)d_in[4];
    const float* w2pw = (const float*)d_in[5];
    const float* wf   = (const float*)d_in[6];
    float* out = (float*)d_out;

    prep_kernel<<<64, 256>>>(w1dw, w1pw, w21, w2dw, w2pw, wf);

    const int smem_bytes = (3 * ROWS * 128 + 128 * 128) * (int)sizeof(float);  // 169,984 B
    cudaFuncSetAttribute(fused_kernel, cudaFuncAttributeMaxDynamicSharedMemorySize, smem_bytes);
    fused_kernel<<<NPOS / TN, NTHREADS, smem_bytes>>>(x, out);
}

// round 12
// speedup vs baseline: 2.9475x; 2.9475x over previous
#include <cuda_runtime.h>
#include <cuda_bf16.h>
#include <cstdint>

#define NPOS   131072
#define TN     64
#define NT     512
#define RS     272                      // padded row stride (bytes) = 136 bf16
#define TROWS  80                       // activation tile rows (72 live + pad)
#define TILEB  (TROWS * RS)             // 21760 B
#define WBYTES (128 * RS)               // 34816 B per 128x128 bf16 weight

// smem byte offsets
#define O_HHI  0
#define O_HLO  (O_HHI + TILEB)
#define O_T1   (O_HLO + TILEB)
#define O_T2   (O_T1 + TILEB)
#define O_WA   (O_T2 + TILEB)           // one weight matrix
#define O_WB   (O_WA + WBYTES)          // two weight matrices (WFh hi+lo)
#define SM_TOTAL (O_WB + 2 * WBYTES)    // 191488 B

// ---------------- prepped weights in device globals (bf16, 272B row stride) --
__device__ __align__(16) unsigned char g_W1[WBYTES];
__device__ __align__(16) unsigned char g_W2[WBYTES];
__device__ __align__(16) unsigned char g_W5[WBYTES];
__device__ __align__(16) unsigned char g_WFh[2 * WBYTES];  // hi at 0, lo at WBYTES
__device__ __align__(16) unsigned char g_WFb[WBYTES];
__device__ float g_dw1[3 * 128];
__device__ float g_dw2[3 * 128];

__global__ void prep_kernel(const float* __restrict__ w1dw, const float* __restrict__ w1pw,
                            const float* __restrict__ w21,  const float* __restrict__ w2dw,
                            const float* __restrict__ w2pw, const float* __restrict__ wf)
{
    int t = blockIdx.x * blockDim.x + threadIdx.x;
    if (t < 128 * 128) {
        int o = t >> 7, i = t & 127;
        uint32_t off = (uint32_t)(o * RS + i * 2);
        *(__nv_bfloat16*)(g_W1 + off) = __float2bfloat16(w1pw[o * 128 + i]);
        *(__nv_bfloat16*)(g_W2 + off) = __float2bfloat16(w21 [o * 128 + i]);
        *(__nv_bfloat16*)(g_W5 + off) = __float2bfloat16(w2pw[o * 128 + i]);
        float wh = wf[o * 256 + i];
        __nv_bfloat16 hh = __float2bfloat16(wh);
        *(__nv_bfloat16*)(g_WFh + off)          = hh;
        *(__nv_bfloat16*)(g_WFh + WBYTES + off) = __float2bfloat16(wh - __bfloat162float(hh));
        *(__nv_bfloat16*)(g_WFb + off) = __float2bfloat16(wf[o * 256 + 128 + i]);
    }
    if (t < 128) {
#pragma unroll
        for (int k = 0; k < 3; k++) {
            g_dw1[k * 128 + t] = w1dw[t * 9 + k * 3 + 1];
            g_dw2[k * 128 + t] = w2dw[t * 9 + k * 3 + 1];
        }
    }
}

// ---------------- threefry (verified round 3: XOR of both output words) -----
__device__ __forceinline__ unsigned tf_bits(unsigned x1)
{
    unsigned x0 = 0u;
    const unsigned k0 = 0u, k1 = 42u;
    const unsigned k2 = 0x1BD11BDAu ^ k0 ^ k1;
#define TF_R(r) { x0 += x1; x1 = __funnelshift_l(x1, x1, (r)); x1 ^= x0; }
    x0 += k0; x1 += k1;
    TF_R(13) TF_R(15) TF_R(26) TF_R(6)
    x0 += k1; x1 += k2 + 1u;
    TF_R(17) TF_R(29) TF_R(16) TF_R(24)
    x0 += k2; x1 += k0 + 2u;
    TF_R(13) TF_R(15) TF_R(26) TF_R(6)
    x0 += k0; x1 += k1 + 3u;
    TF_R(17) TF_R(29) TF_R(16) TF_R(24)
    x0 += k1; x1 += k2 + 4u;
    TF_R(13) TF_R(15) TF_R(26) TF_R(6)
    x0 += k2; x1 += k0 + 5u;
#undef TF_R
    return x0 ^ x1;
}

// ---------------- low-level helpers ----------------
__device__ __forceinline__ uint32_t s2u32(const void* p)
{
    uint32_t a;
    asm("{ .reg .u64 t; cvta.to.shared.u64 t, %1; cvt.u32.u64 %0, t; }" : "=r"(a) : "l"(p));
    return a;
}
__device__ __forceinline__ void cp16(uint32_t dst, const void* src)
{
    asm volatile("cp.async.cg.shared.global [%0], [%1], 16;" :: "r"(dst), "l"(src));
}
__device__ __forceinline__ void cp_commit() { asm volatile("cp.async.commit_group;"); }
template<int N> __device__ __forceinline__ void cp_wait()
{
    asm volatile("cp.async.wait_group %0;" :: "n"(N) : "memory");
}
__device__ __forceinline__ void cp_tile(uint32_t dst, const unsigned char* src, int tid, int bytes)
{
    for (int off = tid * 16; off < bytes; off += NT * 16) cp16(dst + off, src + off);
    cp_commit();
}

#define LDSM4(a0, a1, a2, a3, addr) \
    asm volatile("ldmatrix.sync.aligned.m8n8.x4.shared.b16 {%0,%1,%2,%3}, [%4];" \
                 : "=r"(a0), "=r"(a1), "=r"(a2), "=r"(a3) : "r"(addr))
// NON-transposed: V rows are n with k contiguous, which IS the required
// col-major-B fragment layout (lane l -> n = l/4, k = (l%4)*2 + {0,1}).
#define LDSM2(b0, b1, addr) \
    asm volatile("ldmatrix.sync.aligned.m8n8.x2.shared.b16 {%0,%1}, [%2];" \
                 : "=r"(b0), "=r"(b1) : "r"(addr))
#define MMA16816(d, a0, a1, a2, a3, b0, b1) \
    asm volatile("mma.sync.aligned.m16n8k16.row.col.f32.bf16.bf16.f32 " \
                 "{%0,%1,%2,%3}, {%4,%5,%6,%7}, {%8,%9}, {%0,%1,%2,%3};" \
                 : "+f"((d)[0]), "+f"((d)[1]), "+f"((d)[2]), "+f"((d)[3]) \
                 : "r"(a0), "r"(a1), "r"(a2), "r"(a3), "r"(b0), "r"(b1))

// One full 128(K) GEMM pass: acc[t] += W(16x128 slice) x V(rows n0base+t*8..+7)^T
__device__ __forceinline__ void mma_pass(uint32_t wbase, uint32_t vbase,
                                         float (&acc)[5][4],
                                         int a_off, int b_off, int n0base)
{
#pragma unroll 2
    for (int ks = 0; ks < 8; ks++) {
        uint32_t a0, a1, a2, a3;
        LDSM4(a0, a1, a2, a3, wbase + a_off + ks * 32);
#pragma unroll
        for (int t = 0; t < 5; t++) {
            uint32_t b0, b1;
            LDSM2(b0, b1, vbase + b_off + (n0base + t * 8) * RS + ks * 32);
            MMA16816(acc[t], a0, a1, a2, a3, b0, b1);
        }
    }
}

// ---------------- main fused kernel ----------------
__global__ void __launch_bounds__(NT, 1)
fused_kernel(const float* __restrict__ x, float* __restrict__ out)
{
    extern __shared__ __align__(16) char smem[];
    const uint32_t sb = s2u32(smem);
    const int tid = threadIdx.x;
    const int lane = tid & 31, w = tid >> 5;
    const int o0 = (w & 7) * 16;               // warp's 16 output channels
    const int g = w >> 3;                      // n-half
    const int n0base = g * 40;                 // 5 tiles of 8 rows
    const int g0 = blockIdx.x * TN;

    const uint32_t HHI = sb + O_HHI, HLO = sb + O_HLO;
    const uint32_t T1 = sb + O_T1,   T2 = sb + O_T2;
    const uint32_t WA = sb + O_WA,   WB = sb + O_WB;

    // ldmatrix per-lane offsets
    const int a_off = (o0 + (lane & 15)) * RS + ((lane >> 4) << 4);
    const int bl = lane & 15;
    const int b_off = (bl & 7) * RS + ((bl >> 3) << 4);
    // epilogue cell mapping (m16n8 accum layout)
    const int erow = lane >> 2, ecolp = (lane & 3) * 2;

    // prefetch W1 (g1), W2 (g2)
    cp_tile(WA, g_W1, tid, WBYTES);
    cp_tile(WB, g_W2, tid, WBYTES);

    // load x rows [g0-2, g0+78), split fp32 -> bf16 hi/lo
    for (int idx = tid; idx < TROWS * 32; idx += NT) {
        const int l = idx >> 5, ch = idx & 31;
        const int n = g0 - 2 + l;
        float4 v = make_float4(0.f, 0.f, 0.f, 0.f);
        if ((unsigned)n < (unsigned)NPOS) v = ((const float4*)x)[n * 32 + ch];
        __nv_bfloat162 h0 = __floats2bfloat162_rn(v.x, v.y);
        __nv_bfloat162 h1 = __floats2bfloat162_rn(v.z, v.w);
        __nv_bfloat162 l0 = __floats2bfloat162_rn(v.x - __bfloat162float(h0.x), v.y - __bfloat162float(h0.y));
        __nv_bfloat162 l1 = __floats2bfloat162_rn(v.z - __bfloat162float(h1.x), v.w - __bfloat162float(h1.y));
        *(uint2*)(smem + O_HHI + l * RS + ch * 8) = make_uint2(*(uint32_t*)&h0, *(uint32_t*)&h1);
        *(uint2*)(smem + O_HLO + l * RS + ch * 8) = make_uint2(*(uint32_t*)&l0, *(uint32_t*)&l1);
    }
    __syncthreads();

    // depthwise taps (2 channels per thread)
    const int c2 = tid & 63, rg = tid >> 6;
    const int ca = 2 * c2, cb = 2 * c2 + 1;
    const float a1a = __ldg(&g_dw1[ca]),        a1b = __ldg(&g_dw1[cb]);
    const float b1a_ = __ldg(&g_dw1[128 + ca]), b1b_ = __ldg(&g_dw1[128 + cb]);
    const float c1a = __ldg(&g_dw1[256 + ca]),  c1b = __ldg(&g_dw1[256 + cb]);
    const float a2a = __ldg(&g_dw2[ca]),        a2b = __ldg(&g_dw2[cb]);
    const float b2a_ = __ldg(&g_dw2[128 + ca]), b2b_ = __ldg(&g_dw2[128 + cb]);
    const float c2a = __ldg(&g_dw2[256 + ca]),  c2b = __ldg(&g_dw2[256 + cb]);

    // ---- stage A: b1_dw = relu(dw1(h)) rows [1,66] -> T1 (bf16), fp32 path ----
    for (int l = 1 + rg; l < 67; l += 8) {
        const int om = (l - 1) * RS + 4 * c2, oc = l * RS + 4 * c2, op = (l + 1) * RS + 4 * c2;
        __nv_bfloat162 hm = *(__nv_bfloat162*)(smem + O_HHI + om), lm = *(__nv_bfloat162*)(smem + O_HLO + om);
        __nv_bfloat162 hc = *(__nv_bfloat162*)(smem + O_HHI + oc), lc = *(__nv_bfloat162*)(smem + O_HLO + oc);
        __nv_bfloat162 hp = *(__nv_bfloat162*)(smem + O_HHI + op), lp = *(__nv_bfloat162*)(smem + O_HLO + op);
        float xm0 = __bfloat162float(hm.x) + __bfloat162float(lm.x), xm1 = __bfloat162float(hm.y) + __bfloat162float(lm.y);
        float xc0 = __bfloat162float(hc.x) + __bfloat162float(lc.x), xc1 = __bfloat162float(hc.y) + __bfloat162float(lc.y);
        float xp0 = __bfloat162float(hp.x) + __bfloat162float(lp.x), xp1 = __bfloat162float(hp.y) + __bfloat162float(lp.y);
        float v0 = fmaxf(a1a * xm0 + b1a_ * xc0 + c1a * xp0, 0.f);
        float v1 = fmaxf(a1b * xm1 + b1b_ * xc1 + c1b * xp1, 0.f);
        *(__nv_bfloat162*)(smem + O_T1 + oc) = __floats2bfloat162_rn(v0, v1);
    }
    cp_wait<1>();              // W1 landed
    __syncthreads();           // + T1 ready, W1 visible to all

    // ---- pass B: b1 = relu(W1 x b1_dw), kept in registers ----
    float accB[5][4];
#pragma unroll
    for (int t = 0; t < 5; t++)
#pragma unroll
        for (int r = 0; r < 4; r++) accB[t][r] = 0.f;
    mma_pass(WA, T1, accB, a_off, b_off, n0base);
    float b1v[5][4];
#pragma unroll
    for (int t = 0; t < 5; t++)
#pragma unroll
        for (int r = 0; r < 4; r++) b1v[t][r] = fmaxf(accB[t][r], 0.f);
    __syncthreads();           // all WA reads done
    cp_tile(WA, g_W5, tid, WBYTES);   // g3
    cp_wait<1>();              // W2 landed (g3 outstanding)
    __syncthreads();

    // ---- pass C: b2 = mask * (relu(W2 x h_hi) + b1) -> T2 (bf16) ----
    float accC[5][4];
#pragma unroll
    for (int t = 0; t < 5; t++)
#pragma unroll
        for (int r = 0; r < 4; r++) accC[t][r] = 0.f;
    mma_pass(WB, HHI, accC, a_off, b_off, n0base);
#pragma unroll
    for (int t = 0; t < 5; t++) {
#pragma unroll
        for (int r = 0; r < 4; r++) {
            const int col = n0base + t * 8 + ecolp + (r & 1);
            const int o = o0 + erow + ((r >> 1) << 3);
            if (col >= 1 && col <= 66) {
                const int n = g0 - 2 + col;
                float v = fmaxf(accC[t][r], 0.f) + b1v[t][r];
                if ((unsigned)n < (unsigned)NPOS) {
                    if ((int)tf_bits((unsigned)o * (unsigned)NPOS + (unsigned)n) < 0) v = 0.f;
                } else v = 0.f;
                *(__nv_bfloat16*)(smem + O_T2 + col * RS + o * 2) = __float2bfloat16(v);
            }
        }
    }
    __syncthreads();           // T2 ready, WB reads done
    cp_tile(WB, g_WFh, tid, 2 * WBYTES);  // g4 (hi+lo)

    // ---- stage D: t = relu(dw2(b2)) rows [2,65] -> T1 ----
    for (int l = 2 + rg; l < 66; l += 8) {
        const int om = (l - 1) * RS + 4 * c2, oc = l * RS + 4 * c2, op = (l + 1) * RS + 4 * c2;
        __nv_bfloat162 hm = *(__nv_bfloat162*)(smem + O_T2 + om);
        __nv_bfloat162 hc = *(__nv_bfloat162*)(smem + O_T2 + oc);
        __nv_bfloat162 hp = *(__nv_bfloat162*)(smem + O_T2 + op);
        float v0 = fmaxf(a2a * __bfloat162float(hm.x) + b2a_ * __bfloat162float(hc.x) + c2a * __bfloat162float(hp.x), 0.f);
        float v1 = fmaxf(a2b * __bfloat162float(hm.y) + b2b_ * __bfloat162float(hc.y) + c2b * __bfloat162float(hp.y), 0.f);
        *(__nv_bfloat162*)(smem + O_T1 + oc) = __floats2bfloat162_rn(v0, v1);
    }
    cp_wait<1>();              // W5 landed (g4 outstanding)
    __syncthreads();           // + T1 ready

    // ---- pass E: u = relu(W5 x t) -> T2 ----
    float accE[5][4];
#pragma unroll
    for (int t = 0; t < 5; t++)
#pragma unroll
        for (int r = 0; r < 4; r++) accE[t][r] = 0.f;
    mma_pass(WA, T1, accE, a_off, b_off, n0base);
#pragma unroll
    for (int t = 0; t < 5; t++) {
#pragma unroll
        for (int r = 0; r < 4; r++) {
            const int col = n0base + t * 8 + ecolp + (r & 1);
            const int o = o0 + erow + ((r >> 1) << 3);
            if (col >= 2 && col <= 65)
                *(__nv_bfloat16*)(smem + O_T2 + col * RS + o * 2) =
                    __float2bfloat16(fmaxf(accE[t][r], 0.f));
        }
    }
    __syncthreads();           // T2(u) ready, WA reads done
    cp_tile(WA, g_WFb, tid, WBYTES);  // g5
    cp_wait<0>();              // WFh + WFb landed
    __syncthreads();

    // ---- pass F: out = relu(WFh x h (3-term hi/lo) + WFb x u) ----
    float accF[5][4];
#pragma unroll
    for (int t = 0; t < 5; t++)
#pragma unroll
        for (int r = 0; r < 4; r++) accF[t][r] = 0.f;
    mma_pass(WB, HHI, accF, a_off, b_off, n0base);          // hi x hi
    mma_pass(WB, HLO, accF, a_off, b_off, n0base);          // hi x lo
    mma_pass(WB + WBYTES, HHI, accF, a_off, b_off, n0base); // lo x hi
    mma_pass(WA, T2, accF, a_off, b_off, n0base);           // WFb x u

#pragma unroll
    for (int t = 0; t < 5; t++) {
#pragma unroll
        for (int r = 0; r < 4; r++) {
            const int col = n0base + t * 8 + ecolp + (r & 1);
            const int o = o0 + erow + ((r >> 1) << 3);
            if (col >= 2 && col <= 65) {
                const int n = g0 - 2 + col;
                out[n * 128 + o] = fmaxf(accF[t][r], 0.f);
            }
        }
    }
}

// ---------------------------------------------------------------------------
extern "C" void kernel_launch(void* const* d_in, const int* in_sizes, int n_in,
                              void* d_out, int out_size)
{
    const float* x    = (const float*)d_in[0];
    const float* w1dw = (const float*)d_in[1];
    const float* w1pw = (const float*)d_in[2];
    const float* w21  = (const float*)d_in[3];
    const float* w2dw = (const float*)d_in[4];
    const float* w2pw = (const float*)d_in[5];
    const float* wf   = (const float*)d_in[6];
    float* out = (float*)d_out;

    prep_kernel<<<64, 256>>>(w1dw, w1pw, w21, w2dw, w2pw, wf);

    cudaFuncSetAttribute(fused_kernel, cudaFuncAttributeMaxDynamicSharedMemorySize, SM_TOTAL);
    fused_kernel<<<NPOS / TN, NT, SM_TOTAL>>>(x, out);
}

// round 13
// speedup vs baseline: 2.9950x; 1.0161x over previous
#include <cuda_runtime.h>
#include <cuda_bf16.h>
#include <cstdint>

#define NPOS   131072
#define TN     64
#define NT     512
#define RS     272                      // padded row stride (bytes) = 136 bf16
#define TROWS  80                       // activation tile rows (72 live + pad)
#define TILEB  (TROWS * RS)             // 21760 B
#define WBYTES (128 * RS)               // 34816 B per 128x128 bf16 weight

// smem byte offsets
#define O_HHI  0
#define O_HLO  (O_HHI + TILEB)
#define O_T1   (O_HLO + TILEB)
#define O_T2   (O_T1 + TILEB)
#define O_WA   (O_T2 + TILEB)           // one weight matrix
#define O_WB   (O_WA + WBYTES)          // two weight matrices (WFh hi+lo)
#define SM_TOTAL (O_WB + 2 * WBYTES)    // 191488 B

// ---------------- prepped weights in device globals (bf16, 272B row stride) --
__device__ __align__(16) unsigned char g_W1[WBYTES];
__device__ __align__(16) unsigned char g_W2[WBYTES];
__device__ __align__(16) unsigned char g_W5[WBYTES];
__device__ __align__(16) unsigned char g_WFh[2 * WBYTES];  // hi at 0, lo at WBYTES
__device__ __align__(16) unsigned char g_WFb[WBYTES];
__device__ float g_dw1[3 * 128];
__device__ float g_dw2[3 * 128];

__global__ void prep_kernel(const float* __restrict__ w1dw, const float* __restrict__ w1pw,
                            const float* __restrict__ w21,  const float* __restrict__ w2dw,
                            const float* __restrict__ w2pw, const float* __restrict__ wf)
{
    int t = blockIdx.x * blockDim.x + threadIdx.x;
    if (t < 128 * 128) {
        int o = t >> 7, i = t & 127;
        uint32_t off = (uint32_t)(o * RS + i * 2);
        *(__nv_bfloat16*)(g_W1 + off) = __float2bfloat16(w1pw[o * 128 + i]);
        *(__nv_bfloat16*)(g_W2 + off) = __float2bfloat16(w21 [o * 128 + i]);
        *(__nv_bfloat16*)(g_W5 + off) = __float2bfloat16(w2pw[o * 128 + i]);
        float wh = wf[o * 256 + i];
        __nv_bfloat16 hh = __float2bfloat16(wh);
        *(__nv_bfloat16*)(g_WFh + off)          = hh;
        *(__nv_bfloat16*)(g_WFh + WBYTES + off) = __float2bfloat16(wh - __bfloat162float(hh));
        *(__nv_bfloat16*)(g_WFb + off) = __float2bfloat16(wf[o * 256 + 128 + i]);
    }
    if (t < 128) {
#pragma unroll
        for (int k = 0; k < 3; k++) {
            g_dw1[k * 128 + t] = w1dw[t * 9 + k * 3 + 1];
            g_dw2[k * 128 + t] = w2dw[t * 9 + k * 3 + 1];
        }
    }
}

// ---------------- threefry (verified: XOR of both output words) ----------
__device__ __forceinline__ unsigned tf_bits(unsigned x1)
{
    unsigned x0 = 0u;
    const unsigned k0 = 0u, k1 = 42u;
    const unsigned k2 = 0x1BD11BDAu ^ k0 ^ k1;
#define TF_R(r) { x0 += x1; x1 = __funnelshift_l(x1, x1, (r)); x1 ^= x0; }
    x0 += k0; x1 += k1;
    TF_R(13) TF_R(15) TF_R(26) TF_R(6)
    x0 += k1; x1 += k2 + 1u;
    TF_R(17) TF_R(29) TF_R(16) TF_R(24)
    x0 += k2; x1 += k0 + 2u;
    TF_R(13) TF_R(15) TF_R(26) TF_R(6)
    x0 += k0; x1 += k1 + 3u;
    TF_R(17) TF_R(29) TF_R(16) TF_R(24)
    x0 += k1; x1 += k2 + 4u;
    TF_R(13) TF_R(15) TF_R(26) TF_R(6)
    x0 += k2; x1 += k0 + 5u;
#undef TF_R
    return x0 ^ x1;
}

// ---------------- low-level helpers ----------------
__device__ __forceinline__ uint32_t s2u32(const void* p)
{
    uint32_t a;
    asm("{ .reg .u64 t; cvta.to.shared.u64 t, %1; cvt.u32.u64 %0, t; }" : "=r"(a) : "l"(p));
    return a;
}
__device__ __forceinline__ void cp16(uint32_t dst, const void* src)
{
    asm volatile("cp.async.cg.shared.global [%0], [%1], 16;" :: "r"(dst), "l"(src));
}
__device__ __forceinline__ void cp_commit() { asm volatile("cp.async.commit_group;"); }
template<int N> __device__ __forceinline__ void cp_wait()
{
    asm volatile("cp.async.wait_group %0;" :: "n"(N) : "memory");
}
__device__ __forceinline__ void cp_tile(uint32_t dst, const unsigned char* src, int tid, int bytes)
{
    for (int off = tid * 16; off < bytes; off += NT * 16) cp16(dst + off, src + off);
    cp_commit();
}

#define LDSM4(a0, a1, a2, a3, addr) \
    asm volatile("ldmatrix.sync.aligned.m8n8.x4.shared.b16 {%0,%1,%2,%3}, [%4];" \
                 : "=r"(a0), "=r"(a1), "=r"(a2), "=r"(a3) : "r"(addr))
#define LDSM2(b0, b1, addr) \
    asm volatile("ldmatrix.sync.aligned.m8n8.x2.shared.b16 {%0,%1}, [%2];" \
                 : "=r"(b0), "=r"(b1) : "r"(addr))
#define MMA16816(d, a0, a1, a2, a3, b0, b1) \
    asm volatile("mma.sync.aligned.m16n8k16.row.col.f32.bf16.bf16.f32 " \
                 "{%0,%1,%2,%3}, {%4,%5,%6,%7}, {%8,%9}, {%0,%1,%2,%3};" \
                 : "+f"((d)[0]), "+f"((d)[1]), "+f"((d)[2]), "+f"((d)[3]) \
                 : "r"(a0), "r"(a1), "r"(a2), "r"(a3), "r"(b0), "r"(b1))

// Load B fragments for one 16-wide k-step: tiles 0-3 via two x4 (2 tiles each),
// tile 4 via x2 (skipped when dead). vb4/vb2 are per-lane addresses at k-step 0.
__device__ __forceinline__ void load_B5(uint32_t vb4, uint32_t vb2, uint32_t (&b)[10], bool tail)
{
    LDSM4(b[0], b[1], b[2], b[3], vb4);
    LDSM4(b[4], b[5], b[6], b[7], vb4 + 16 * RS);
    if (tail) LDSM2(b[8], b[9], vb2);
}
__device__ __forceinline__ void mma5(float (&acc)[5][4], const uint32_t (&a)[4],
                                     const uint32_t (&b)[10], bool tail)
{
#pragma unroll
    for (int t = 0; t < 4; t++)
        MMA16816(acc[t], a[0], a[1], a[2], a[3], b[2 * t], b[2 * t + 1]);
    if (tail) MMA16816(acc[4], a[0], a[1], a[2], a[3], b[8], b[9]);
}
__device__ __forceinline__ void zero5(float (&acc)[5][4])
{
#pragma unroll
    for (int t = 0; t < 5; t++)
#pragma unroll
        for (int r = 0; r < 4; r++) acc[t][r] = 0.f;
}

// ---------------- main fused kernel ----------------
__global__ void __launch_bounds__(NT, 1)
fused_kernel(const float* __restrict__ x, float* __restrict__ out)
{
    extern __shared__ __align__(16) char smem[];
    const uint32_t sb = s2u32(smem);
    const int tid = threadIdx.x;
    const int lane = tid & 31, w = tid >> 5;
    const int o0 = (w & 7) * 16;               // warp's 16 output channels
    const int g = w >> 3;                      // n-half
    const int n0base = g * 40;                 // up to 5 tiles of 8 rows
    const bool tail = (g == 0);                // g=1 tile4 (rows 72-79) is all-dead
    const int g0 = blockIdx.x * TN;

    const uint32_t HHI = sb + O_HHI, HLO = sb + O_HLO;
    const uint32_t T1 = sb + O_T1,   T2 = sb + O_T2;
    const uint32_t WA = sb + O_WA,   WB = sb + O_WB;

    // ldmatrix per-lane offsets
    const int a_off = (o0 + (lane & 15)) * RS + ((lane >> 4) << 4);
    // B x4 (2 n-tiles, both k-halves): lanes 0-7 -> tile0 k0-7, 8-15 -> tile0 k8-15,
    // 16-23 -> tile1 k0-7, 24-31 -> tile1 k8-15
    const int b4_off = (lane & 7) * RS + (((lane >> 4) & 1) * 8) * RS + ((lane >> 3) & 1) * 16;
    const int bl = lane & 15;
    const int b2_off = (bl & 7) * RS + ((bl >> 3) << 4);
    // epilogue cell mapping (m16n8 accum layout)
    const int erow = lane >> 2, ecolp = (lane & 3) * 2;

    // per-warp B base addresses (at k-step 0)
    const uint32_t vHHI4 = HHI + n0base * RS + b4_off, vHHI2 = HHI + (n0base + 32) * RS + b2_off;
    const uint32_t vHLO4 = HLO + n0base * RS + b4_off, vHLO2 = HLO + (n0base + 32) * RS + b2_off;
    const uint32_t vT14  = T1 + n0base * RS + b4_off,  vT12  = T1 + (n0base + 32) * RS + b2_off;
    const uint32_t vT24  = T2 + n0base * RS + b4_off,  vT22  = T2 + (n0base + 32) * RS + b2_off;

    // prefetch W1 (g1), W2 (g2)
    cp_tile(WA, g_W1, tid, WBYTES);
    cp_tile(WB, g_W2, tid, WBYTES);

    // load x rows [g0-2, g0+78), split fp32 -> bf16 hi/lo
    for (int idx = tid; idx < TROWS * 32; idx += NT) {
        const int l = idx >> 5, ch = idx & 31;
        const int n = g0 - 2 + l;
        float4 v = make_float4(0.f, 0.f, 0.f, 0.f);
        if ((unsigned)n < (unsigned)NPOS) v = ((const float4*)x)[n * 32 + ch];
        __nv_bfloat162 h0 = __floats2bfloat162_rn(v.x, v.y);
        __nv_bfloat162 h1 = __floats2bfloat162_rn(v.z, v.w);
        __nv_bfloat162 l0 = __floats2bfloat162_rn(v.x - __bfloat162float(h0.x), v.y - __bfloat162float(h0.y));
        __nv_bfloat162 l1 = __floats2bfloat162_rn(v.z - __bfloat162float(h1.x), v.w - __bfloat162float(h1.y));
        *(uint2*)(smem + O_HHI + l * RS + ch * 8) = make_uint2(*(uint32_t*)&h0, *(uint32_t*)&h1);
        *(uint2*)(smem + O_HLO + l * RS + ch * 8) = make_uint2(*(uint32_t*)&l0, *(uint32_t*)&l1);
    }

    // ---- precompute threefry mask bits (overlaps cp.async + x-load shadow) ----
    unsigned mbits = 0;
#pragma unroll
    for (int t = 0; t < 5; t++) {
#pragma unroll
        for (int r = 0; r < 4; r++) {
            const int col = n0base + t * 8 + ecolp + (r & 1);
            if (col < 1 || col > 66) continue;
            const int n = g0 - 2 + col;
            const int och = o0 + erow + ((r >> 1) << 3);
            if ((unsigned)n < (unsigned)NPOS &&
                (int)tf_bits((unsigned)och * (unsigned)NPOS + (unsigned)n) < 0)
                mbits |= 1u << (t * 4 + r);
        }
    }
    __syncthreads();

    // depthwise taps (2 channels per thread)
    const int c2 = tid & 63, rg = tid >> 6;
    const int ca = 2 * c2, cb = 2 * c2 + 1;
    const float a1a = __ldg(&g_dw1[ca]),        a1b = __ldg(&g_dw1[cb]);
    const float b1a_ = __ldg(&g_dw1[128 + ca]), b1b_ = __ldg(&g_dw1[128 + cb]);
    const float c1a = __ldg(&g_dw1[256 + ca]),  c1b = __ldg(&g_dw1[256 + cb]);
    const float a2a = __ldg(&g_dw2[ca]),        a2b = __ldg(&g_dw2[cb]);
    const float b2a_ = __ldg(&g_dw2[128 + ca]), b2b_ = __ldg(&g_dw2[128 + cb]);
    const float c2a = __ldg(&g_dw2[256 + ca]),  c2b = __ldg(&g_dw2[256 + cb]);

    // ---- stage A: b1_dw = relu(dw1(h)) rows [1,66] -> T1 (bf16), fp32 path ----
    for (int l = 1 + rg; l < 67; l += 8) {
        const int om = (l - 1) * RS + 4 * c2, oc = l * RS + 4 * c2, op = (l + 1) * RS + 4 * c2;
        __nv_bfloat162 hm = *(__nv_bfloat162*)(smem + O_HHI + om), lm = *(__nv_bfloat162*)(smem + O_HLO + om);
        __nv_bfloat162 hc = *(__nv_bfloat162*)(smem + O_HHI + oc), lc = *(__nv_bfloat162*)(smem + O_HLO + oc);
        __nv_bfloat162 hp = *(__nv_bfloat162*)(smem + O_HHI + op), lp = *(__nv_bfloat162*)(smem + O_HLO + op);
        float xm0 = __bfloat162float(hm.x) + __bfloat162float(lm.x), xm1 = __bfloat162float(hm.y) + __bfloat162float(lm.y);
        float xc0 = __bfloat162float(hc.x) + __bfloat162float(lc.x), xc1 = __bfloat162float(hc.y) + __bfloat162float(lc.y);
        float xp0 = __bfloat162float(hp.x) + __bfloat162float(lp.x), xp1 = __bfloat162float(hp.y) + __bfloat162float(lp.y);
        float v0 = fmaxf(a1a * xm0 + b1a_ * xc0 + c1a * xp0, 0.f);
        float v1 = fmaxf(a1b * xm1 + b1b_ * xc1 + c1b * xp1, 0.f);
        *(__nv_bfloat162*)(smem + O_T1 + oc) = __floats2bfloat162_rn(v0, v1);
    }
    cp_wait<0>();              // W1 + W2 landed
    __syncthreads();           // + T1 ready

    // ---- merged passes B+C: accB = W1 x b1_dw, accC = W2 x h_hi (independent) ----
    float accB[5][4], accC[5][4];
    zero5(accB); zero5(accC);
    {
        const uint32_t wa = WA + a_off, wb = WB + a_off;
#pragma unroll 2
        for (int ks = 0; ks < 8; ks++) {
            uint32_t a1[4], a2[4], bT[10], bH[10];
            LDSM4(a1[0], a1[1], a1[2], a1[3], wa + ks * 32);
            LDSM4(a2[0], a2[1], a2[2], a2[3], wb + ks * 32);
            load_B5(vT14 + ks * 32, vT12 + ks * 32, bT, tail);
            load_B5(vHHI4 + ks * 32, vHHI2 + ks * 32, bH, tail);
            mma5(accB, a1, bT, tail);
            mma5(accC, a2, bH, tail);
        }
    }
    // epilogue BC: b2 = mask * (relu(accC) + relu(accB)) -> T2 (bf16)
#pragma unroll
    for (int t = 0; t < 5; t++) {
#pragma unroll
        for (int r = 0; r < 4; r++) {
            const int col = n0base + t * 8 + ecolp + (r & 1);
            const int o = o0 + erow + ((r >> 1) << 3);
            if (col >= 1 && col <= 66) {
                float v = fmaxf(accC[t][r], 0.f) + fmaxf(accB[t][r], 0.f);
                if ((mbits >> (t * 4 + r)) & 1) v = 0.f;
                const int n = g0 - 2 + col;
                if ((unsigned)n >= (unsigned)NPOS) v = 0.f;
                *(__nv_bfloat16*)(smem + O_T2 + col * RS + o * 2) = __float2bfloat16(v);
            }
        }
    }
    __syncthreads();           // T2 ready, WA/WB reads done
    cp_tile(WA, g_W5, tid, WBYTES);        // g3
    cp_tile(WB, g_WFh, tid, 2 * WBYTES);   // g4 (hi+lo)

    // ---- stage D: t = relu(dw2(b2)) rows [2,65] -> T1 ----
    for (int l = 2 + rg; l < 66; l += 8) {
        const int om = (l - 1) * RS + 4 * c2, oc = l * RS + 4 * c2, op = (l + 1) * RS + 4 * c2;
        __nv_bfloat162 hm = *(__nv_bfloat162*)(smem + O_T2 + om);
        __nv_bfloat162 hc = *(__nv_bfloat162*)(smem + O_T2 + oc);
        __nv_bfloat162 hp = *(__nv_bfloat162*)(smem + O_T2 + op);
        float v0 = fmaxf(a2a * __bfloat162float(hm.x) + b2a_ * __bfloat162float(hc.x) + c2a * __bfloat162float(hp.x), 0.f);
        float v1 = fmaxf(a2b * __bfloat162float(hm.y) + b2b_ * __bfloat162float(hc.y) + c2b * __bfloat162float(hp.y), 0.f);
        *(__nv_bfloat162*)(smem + O_T1 + oc) = __floats2bfloat162_rn(v0, v1);
    }
    cp_wait<1>();              // W5 landed (WFh outstanding)
    __syncthreads();           // + T1 ready

    // ---- pass E: u = relu(W5 x t) -> T2 ----
    float accE[5][4];
    zero5(accE);
    {
        const uint32_t wa = WA + a_off;
#pragma unroll 2
        for (int ks = 0; ks < 8; ks++) {
            uint32_t a1[4], bT[10];
            LDSM4(a1[0], a1[1], a1[2], a1[3], wa + ks * 32);
            load_B5(vT14 + ks * 32, vT12 + ks * 32, bT, tail);
            mma5(accE, a1, bT, tail);
        }
    }
#pragma unroll
    for (int t = 0; t < 5; t++) {
#pragma unroll
        for (int r = 0; r < 4; r++) {
            const int col = n0base + t * 8 + ecolp + (r & 1);
            const int o = o0 + erow + ((r >> 1) << 3);
            if (col >= 2 && col <= 65)
                *(__nv_bfloat16*)(smem + O_T2 + col * RS + o * 2) =
                    __float2bfloat16(fmaxf(accE[t][r], 0.f));
        }
    }
    __syncthreads();           // T2(u) ready, WA reads done
    cp_tile(WA, g_WFb, tid, WBYTES);  // g5
    cp_wait<0>();              // WFh + WFb landed
    __syncthreads();

    // ---- merged pass F: out = relu(WFh x h (3-term hi/lo) + WFb x u) ----
    // B fragments of HHI shared between the WFh_hi and WFh_lo terms.
    float accF[5][4];
    zero5(accF);
    {
        const uint32_t whh = WB + a_off, whl = WB + WBYTES + a_off, wfb = WA + a_off;
#pragma unroll 1
        for (int ks = 0; ks < 8; ks++) {
            uint32_t ah[4], al[4], ab[4], bH[10], bL[10], bU[10];
            LDSM4(ah[0], ah[1], ah[2], ah[3], whh + ks * 32);
            LDSM4(al[0], al[1], al[2], al[3], whl + ks * 32);
            LDSM4(ab[0], ab[1], ab[2], ab[3], wfb + ks * 32);
            load_B5(vHHI4 + ks * 32, vHHI2 + ks * 32, bH, tail);
            load_B5(vHLO4 + ks * 32, vHLO2 + ks * 32, bL, tail);
            load_B5(vT24 + ks * 32, vT22 + ks * 32, bU, tail);
            mma5(accF, ah, bH, tail);   // hi x hi
            mma5(accF, ah, bL, tail);   // hi x lo
            mma5(accF, al, bH, tail);   // lo x hi
            mma5(accF, ab, bU, tail);   // WFb x u
        }
    }
#pragma unroll
    for (int t = 0; t < 5; t++) {
#pragma unroll
        for (int r = 0; r < 4; r++) {
            const int col = n0base + t * 8 + ecolp + (r & 1);
            const int o = o0 + erow + ((r >> 1) << 3);
            if (col >= 2 && col <= 65) {
                const int n = g0 - 2 + col;
                out[n * 128 + o] = fmaxf(accF[t][r], 0.f);
            }
        }
    }
}

// ---------------------------------------------------------------------------
extern "C" void kernel_launch(void* const* d_in, const int* in_sizes, int n_in,
                              void* d_out, int out_size)
{
    const float* x    = (const float*)d_in[0];
    const float* w1dw = (const float*)d_in[1];
    const float* w1pw = (const float*)d_in[2];
    const float* w21  = (const float*)d_in[3];
    const float* w2dw = (const float*)d_in[4];
    const float* w2pw = (const float*)d_in[5];
    const float* wf   = (const float*)d_in[6];
    float* out = (float*)d_out;

    prep_kernel<<<64, 256>>>(w1dw, w1pw, w21, w2dw, w2pw, wf);

    cudaFuncSetAttribute(fused_kernel, cudaFuncAttributeMaxDynamicSharedMemorySize, SM_TOTAL);
    fused_kernel<<<NPOS / TN, NT, SM_TOTAL>>>(x, out);
}

// round 17
// speedup vs baseline: 3.3360x; 1.1139x over previous
#include <cuda_runtime.h>
#include <cuda_bf16.h>
#include <cstdint>

#define NPOS   131072
#define TN     32                       // output rows per CTA
#define NT     256                      // 8 warps
#define RS     272                      // padded row stride (bytes) = 136 bf16
#define TROWS  40                       // activation tile rows (36 live + pad)
#define TILEB  (TROWS * RS)             // 10880 B
#define WBYTES (128 * RS)               // 34816 B per 128x128 bf16 weight

// smem byte offsets
#define O_HHI  0
#define O_HLO  (O_HHI + TILEB)
#define O_T1   (O_HLO + TILEB)
#define O_T2   (O_T1 + TILEB)
#define O_WA   (O_T2 + TILEB)           // weight buffer A
#define O_WB   (O_WA + WBYTES)          // weight buffer B
#define SM_TOTAL (O_WB + WBYTES)        // 113152 B -> 2 CTAs/SM

// ---------------- prepped weights in device globals (bf16, 272B row stride) --
__device__ __align__(16) unsigned char g_W1[WBYTES];
__device__ __align__(16) unsigned char g_W2[WBYTES];
__device__ __align__(16) unsigned char g_W5[WBYTES];
__device__ __align__(16) unsigned char g_WFh[2 * WBYTES];  // hi at 0, lo at WBYTES
__device__ __align__(16) unsigned char g_WFb[WBYTES];
__device__ float g_dw1[3 * 128];
__device__ float g_dw2[3 * 128];

__global__ void prep_kernel(const float* __restrict__ w1dw, const float* __restrict__ w1pw,
                            const float* __restrict__ w21,  const float* __restrict__ w2dw,
                            const float* __restrict__ w2pw, const float* __restrict__ wf)
{
    int t = blockIdx.x * blockDim.x + threadIdx.x;
    if (t < 128 * 128) {
        int o = t >> 7, i = t & 127;
        uint32_t off = (uint32_t)(o * RS + i * 2);
        *(__nv_bfloat16*)(g_W1 + off) = __float2bfloat16(w1pw[o * 128 + i]);
        *(__nv_bfloat16*)(g_W2 + off) = __float2bfloat16(w21 [o * 128 + i]);
        *(__nv_bfloat16*)(g_W5 + off) = __float2bfloat16(w2pw[o * 128 + i]);
        float wh = wf[o * 256 + i];
        __nv_bfloat16 hh = __float2bfloat16(wh);
        *(__nv_bfloat16*)(g_WFh + off)          = hh;
        *(__nv_bfloat16*)(g_WFh + WBYTES + off) = __float2bfloat16(wh - __bfloat162float(hh));
        *(__nv_bfloat16*)(g_WFb + off) = __float2bfloat16(wf[o * 256 + 128 + i]);
    }
    if (t < 128) {
#pragma unroll
        for (int k = 0; k < 3; k++) {
            g_dw1[k * 128 + t] = w1dw[t * 9 + k * 3 + 1];
            g_dw2[k * 128 + t] = w2dw[t * 9 + k * 3 + 1];
        }
    }
}

// ---------------- threefry (verified: XOR of both output words) ----------
__device__ __forceinline__ unsigned tf_bits(unsigned x1)
{
    unsigned x0 = 0u;
    const unsigned k0 = 0u, k1 = 42u;
    const unsigned k2 = 0x1BD11BDAu ^ k0 ^ k1;
#define TF_R(r) { x0 += x1; x1 = __funnelshift_l(x1, x1, (r)); x1 ^= x0; }
    x0 += k0; x1 += k1;
    TF_R(13) TF_R(15) TF_R(26) TF_R(6)
    x0 += k1; x1 += k2 + 1u;
    TF_R(17) TF_R(29) TF_R(16) TF_R(24)
    x0 += k2; x1 += k0 + 2u;
    TF_R(13) TF_R(15) TF_R(26) TF_R(6)
    x0 += k0; x1 += k1 + 3u;
    TF_R(17) TF_R(29) TF_R(16) TF_R(24)
    x0 += k1; x1 += k2 + 4u;
    TF_R(13) TF_R(15) TF_R(26) TF_R(6)
    x0 += k2; x1 += k0 + 5u;
#undef TF_R
    return x0 ^ x1;
}

// ---------------- low-level helpers ----------------
__device__ __forceinline__ uint32_t s2u32(const void* p)
{
    uint32_t a;
    asm("{ .reg .u64 t; cvta.to.shared.u64 t, %1; cvt.u32.u64 %0, t; }" : "=r"(a) : "l"(p));
    return a;
}
__device__ __forceinline__ void cp16(uint32_t dst, const void* src)
{
    asm volatile("cp.async.cg.shared.global [%0], [%1], 16;" :: "r"(dst), "l"(src));
}
__device__ __forceinline__ void cp_commit() { asm volatile("cp.async.commit_group;"); }
template<int N> __device__ __forceinline__ void cp_wait()
{
    asm volatile("cp.async.wait_group %0;" :: "n"(N) : "memory");
}
__device__ __forceinline__ void cp_tile(uint32_t dst, const unsigned char* src, int tid, int bytes)
{
    for (int off = tid * 16; off < bytes; off += NT * 16) cp16(dst + off, src + off);
    cp_commit();
}

#define LDSM4(a0, a1, a2, a3, addr) \
    asm volatile("ldmatrix.sync.aligned.m8n8.x4.shared.b16 {%0,%1,%2,%3}, [%4];" \
                 : "=r"(a0), "=r"(a1), "=r"(a2), "=r"(a3) : "r"(addr))
#define LDSM2(b0, b1, addr) \
    asm volatile("ldmatrix.sync.aligned.m8n8.x2.shared.b16 {%0,%1}, [%2];" \
                 : "=r"(b0), "=r"(b1) : "r"(addr))
#define MMA16816(d, a0, a1, a2, a3, b0, b1) \
    asm volatile("mma.sync.aligned.m16n8k16.row.col.f32.bf16.bf16.f32 " \
                 "{%0,%1,%2,%3}, {%4,%5,%6,%7}, {%8,%9}, {%0,%1,%2,%3};" \
                 : "+f"((d)[0]), "+f"((d)[1]), "+f"((d)[2]), "+f"((d)[3]) \
                 : "r"(a0), "r"(a1), "r"(a2), "r"(a3), "r"(b0), "r"(b1))

// Load B fragments for one 16-wide k-step over all 5 n-tiles (rows 0-39):
// tiles 0-3 via two x4 (2 tiles each), tile 4 via x2.
__device__ __forceinline__ void load_B5(uint32_t vb4, uint32_t vb2, uint32_t (&b)[10])
{
    LDSM4(b[0], b[1], b[2], b[3], vb4);
    LDSM4(b[4], b[5], b[6], b[7], vb4 + 16 * RS);
    LDSM2(b[8], b[9], vb2);
}
__device__ __forceinline__ void mma5(float (&acc)[5][4], const uint32_t (&a)[4],
                                     const uint32_t (&b)[10])
{
#pragma unroll
    for (int t = 0; t < 5; t++)
        MMA16816(acc[t], a[0], a[1], a[2], a[3], b[2 * t], b[2 * t + 1]);
}
__device__ __forceinline__ void zero5(float (&acc)[5][4])
{
#pragma unroll
    for (int t = 0; t < 5; t++)
#pragma unroll
        for (int r = 0; r < 4; r++) acc[t][r] = 0.f;
}

// ---------------- main fused kernel ----------------
__global__ void __launch_bounds__(NT, 2)
fused_kernel(const float* __restrict__ x, float* __restrict__ out)
{
    extern __shared__ __align__(16) char smem[];
    const uint32_t sb = s2u32(smem);
    const int tid = threadIdx.x;
    const int lane = tid & 31, w = tid >> 5;   // 8 warps
    const int o0 = w * 16;                     // warp's 16 output channels
    const int g0 = blockIdx.x * TN;

    const uint32_t HHI = sb + O_HHI, HLO = sb + O_HLO;
    const uint32_t T1 = sb + O_T1,   T2 = sb + O_T2;
    const uint32_t WA = sb + O_WA,   WB = sb + O_WB;

    // ldmatrix per-lane offsets
    const int a_off = (o0 + (lane & 15)) * RS + ((lane >> 4) << 4);
    // B x4 (2 n-tiles, both k-halves)
    const int b4_off = (lane & 7) * RS + (((lane >> 4) & 1) * 8) * RS + ((lane >> 3) & 1) * 16;
    const int bl = lane & 15;
    const int b2_off = (bl & 7) * RS + ((bl >> 3) << 4);
    // epilogue cell mapping (m16n8 accum layout)
    const int erow = lane >> 2, ecolp = (lane & 3) * 2;

    // per-warp B base addresses (k-step 0); x2 covers tile 4 (rows 32-39)
    const uint32_t vHHI4 = HHI + b4_off, vHHI2 = HHI + 32 * RS + b2_off;
    const uint32_t vHLO4 = HLO + b4_off, vHLO2 = HLO + 32 * RS + b2_off;
    const uint32_t vT14  = T1 + b4_off,  vT12  = T1 + 32 * RS + b2_off;
    const uint32_t vT24  = T2 + b4_off,  vT22  = T2 + 32 * RS + b2_off;

    // prefetch W1 (g1), W2 (g2)
    cp_tile(WA, g_W1, tid, WBYTES);
    cp_tile(WB, g_W2, tid, WBYTES);

    // load x rows [g0-2, g0+38), split fp32 -> bf16 hi/lo
    for (int idx = tid; idx < TROWS * 32; idx += NT) {
        const int l = idx >> 5, ch = idx & 31;
        const int n = g0 - 2 + l;
        float4 v = make_float4(0.f, 0.f, 0.f, 0.f);
        if ((unsigned)n < (unsigned)NPOS) v = ((const float4*)x)[n * 32 + ch];
        __nv_bfloat162 h0 = __floats2bfloat162_rn(v.x, v.y);
        __nv_bfloat162 h1 = __floats2bfloat162_rn(v.z, v.w);
        __nv_bfloat162 l0 = __floats2bfloat162_rn(v.x - __bfloat162float(h0.x), v.y - __bfloat162float(h0.y));
        __nv_bfloat162 l1 = __floats2bfloat162_rn(v.z - __bfloat162float(h1.x), v.w - __bfloat162float(h1.y));
        *(uint2*)(smem + O_HHI + l * RS + ch * 8) = make_uint2(*(uint32_t*)&h0, *(uint32_t*)&h1);
        *(uint2*)(smem + O_HLO + l * RS + ch * 8) = make_uint2(*(uint32_t*)&l0, *(uint32_t*)&l1);
    }

    // ---- precompute threefry mask bits (overlaps cp.async + x-load shadow) ----
    unsigned mbits = 0;
#pragma unroll
    for (int t = 0; t < 5; t++) {
#pragma unroll
        for (int r = 0; r < 4; r++) {
            const int col = t * 8 + ecolp + (r & 1);
            if (col < 1 || col > 34) continue;
            const int n = g0 - 2 + col;
            const int och = o0 + erow + ((r >> 1) << 3);
            if ((unsigned)n < (unsigned)NPOS &&
                (int)tf_bits((unsigned)och * (unsigned)NPOS + (unsigned)n) < 0)
                mbits |= 1u << (t * 4 + r);
        }
    }
    __syncthreads();

    // depthwise taps (2 channels per thread, 4 row-groups)
    const int c2 = tid & 63, rg = tid >> 6;
    const int ca = 2 * c2, cb = 2 * c2 + 1;
    const float a1a = __ldg(&g_dw1[ca]),        a1b = __ldg(&g_dw1[cb]);
    const float b1a_ = __ldg(&g_dw1[128 + ca]), b1b_ = __ldg(&g_dw1[128 + cb]);
    const float c1a = __ldg(&g_dw1[256 + ca]),  c1b = __ldg(&g_dw1[256 + cb]);
    const float a2a = __ldg(&g_dw2[ca]),        a2b = __ldg(&g_dw2[cb]);
    const float b2a_ = __ldg(&g_dw2[128 + ca]), b2b_ = __ldg(&g_dw2[128 + cb]);
    const float c2a = __ldg(&g_dw2[256 + ca]),  c2b = __ldg(&g_dw2[256 + cb]);

    // ---- stage A: b1_dw = relu(dw1(h)) rows [1,34] -> T1 (bf16), fp32 path ----
    for (int l = 1 + rg; l < 35; l += 4) {
        const int om = (l - 1) * RS + 4 * c2, oc = l * RS + 4 * c2, op = (l + 1) * RS + 4 * c2;
        __nv_bfloat162 hm = *(__nv_bfloat162*)(smem + O_HHI + om), lm = *(__nv_bfloat162*)(smem + O_HLO + om);
        __nv_bfloat162 hc = *(__nv_bfloat162*)(smem + O_HHI + oc), lc = *(__nv_bfloat162*)(smem + O_HLO + oc);
        __nv_bfloat162 hp = *(__nv_bfloat162*)(smem + O_HHI + op), lp = *(__nv_bfloat162*)(smem + O_HLO + op);
        float xm0 = __bfloat162float(hm.x) + __bfloat162float(lm.x), xm1 = __bfloat162float(hm.y) + __bfloat162float(lm.y);
        float xc0 = __bfloat162float(hc.x) + __bfloat162float(lc.x), xc1 = __bfloat162float(hc.y) + __bfloat162float(lc.y);
        float xp0 = __bfloat162float(hp.x) + __bfloat162float(lp.x), xp1 = __bfloat162float(hp.y) + __bfloat162float(lp.y);
        float v0 = fmaxf(a1a * xm0 + b1a_ * xc0 + c1a * xp0, 0.f);
        float v1 = fmaxf(a1b * xm1 + b1b_ * xc1 + c1b * xp1, 0.f);
        *(__nv_bfloat162*)(smem + O_T1 + oc) = __floats2bfloat162_rn(v0, v1);
    }
    cp_wait<0>();              // W1 + W2 landed
    __syncthreads();           // + T1 ready

    // ---- merged passes B+C: accB = W1 x b1_dw, accC = W2 x h_hi ----
    float accB[5][4], accC[5][4];
    zero5(accB); zero5(accC);
    {
        const uint32_t wa = WA + a_off, wb = WB + a_off;
#pragma unroll 2
        for (int ks = 0; ks < 8; ks++) {
            uint32_t a1[4], a2[4], bT[10], bH[10];
            LDSM4(a1[0], a1[1], a1[2], a1[3], wa + ks * 32);
            LDSM4(a2[0], a2[1], a2[2], a2[3], wb + ks * 32);
            load_B5(vT14 + ks * 32, vT12 + ks * 32, bT);
            load_B5(vHHI4 + ks * 32, vHHI2 + ks * 32, bH);
            mma5(accB, a1, bT);
            mma5(accC, a2, bH);
        }
    }
    // epilogue BC: b2 = mask * (relu(accC) + relu(accB)) -> T2 (bf16) cols 1..34
#pragma unroll
    for (int t = 0; t < 5; t++) {
#pragma unroll
        for (int r = 0; r < 4; r++) {
            const int col = t * 8 + ecolp + (r & 1);
            const int o = o0 + erow + ((r >> 1) << 3);
            if (col >= 1 && col <= 34) {
                float v = fmaxf(accC[t][r], 0.f) + fmaxf(accB[t][r], 0.f);
                if ((mbits >> (t * 4 + r)) & 1) v = 0.f;
                const int n = g0 - 2 + col;
                if ((unsigned)n >= (unsigned)NPOS) v = 0.f;
                *(__nv_bfloat16*)(smem + O_T2 + col * RS + o * 2) = __float2bfloat16(v);
            }
        }
    }
    __syncthreads();           // T2 ready, WA/WB reads done
    cp_tile(WA, g_W5, tid, WBYTES);        // g3
    cp_tile(WB, g_WFh, tid, WBYTES);       // g4 (WFh hi)

    // ---- stage D: t = relu(dw2(b2)) rows [2,33] -> T1 ----
    for (int l = 2 + rg; l < 34; l += 4) {
        const int om = (l - 1) * RS + 4 * c2, oc = l * RS + 4 * c2, op = (l + 1) * RS + 4 * c2;
        __nv_bfloat162 hm = *(__nv_bfloat162*)(smem + O_T2 + om);
        __nv_bfloat162 hc = *(__nv_bfloat162*)(smem + O_T2 + oc);
        __nv_bfloat162 hp = *(__nv_bfloat162*)(smem + O_T2 + op);
        float v0 = fmaxf(a2a * __bfloat162float(hm.x) + b2a_ * __bfloat162float(hc.x) + c2a * __bfloat162float(hp.x), 0.f);
        float v1 = fmaxf(a2b * __bfloat162float(hm.y) + b2b_ * __bfloat162float(hc.y) + c2b * __bfloat162float(hp.y), 0.f);
        *(__nv_bfloat162*)(smem + O_T1 + oc) = __floats2bfloat162_rn(v0, v1);
    }
    cp_wait<1>();              // W5 landed (WFh-hi outstanding)
    __syncthreads();           // + T1 ready

    // ---- pass E: u = relu(W5 x t) -> T2 cols 2..33 ----
    float accE[5][4];
    zero5(accE);
    {
        const uint32_t wa = WA + a_off;
#pragma unroll 2
        for (int ks = 0; ks < 8; ks++) {
            uint32_t a1[4], bT[10];
            LDSM4(a1[0], a1[1], a1[2], a1[3], wa + ks * 32);
            load_B5(vT14 + ks * 32, vT12 + ks * 32, bT);
            mma5(accE, a1, bT);
        }
    }
#pragma unroll
    for (int t = 0; t < 5; t++) {
#pragma unroll
        for (int r = 0; r < 4; r++) {
            const int col = t * 8 + ecolp + (r & 1);
            const int o = o0 + erow + ((r >> 1) << 3);
            if (col >= 2 && col <= 33)
                *(__nv_bfloat16*)(smem + O_T2 + col * RS + o * 2) =
                    __float2bfloat16(fmaxf(accE[t][r], 0.f));
        }
    }
    __syncthreads();           // T2(u) ready, WA(W5) reads done
    cp_tile(WA, g_WFh + WBYTES, tid, WBYTES);  // g5 (WFh lo -> WA)
    cp_wait<1>();              // g4 (WFh hi) landed
    __syncthreads();

    // ---- pass F1: accF = WFhh x HHI + WFhh x HLO ----
    float accF[5][4];
    zero5(accF);
    {
        const uint32_t whh = WB + a_off;
#pragma unroll 2
        for (int ks = 0; ks < 8; ks++) {
            uint32_t ah[4], bH[10], bL[10];
            LDSM4(ah[0], ah[1], ah[2], ah[3], whh + ks * 32);
            load_B5(vHHI4 + ks * 32, vHHI2 + ks * 32, bH);
            load_B5(vHLO4 + ks * 32, vHLO2 + ks * 32, bL);
            mma5(accF, ah, bH);
            mma5(accF, ah, bL);
        }
    }
    __syncthreads();           // WB (WFhh) reads done
    cp_tile(WB, g_WFb, tid, WBYTES);  // g6 (WFb -> WB)
    cp_wait<1>();              // g5 (WFh lo) landed
    __syncthreads();

    // ---- pass F2: accF += WFhl x HHI ----
    {
        const uint32_t whl = WA + a_off;
#pragma unroll 2
        for (int ks = 0; ks < 8; ks++) {
            uint32_t al[4], bH[10];
            LDSM4(al[0], al[1], al[2], al[3], whl + ks * 32);
            load_B5(vHHI4 + ks * 32, vHHI2 + ks * 32, bH);
            mma5(accF, al, bH);
        }
    }
    cp_wait<0>();              // g6 (WFb) landed
    __syncthreads();

    // ---- pass F3: accF += WFb x u; write out ----
    {
        const uint32_t wfb = WB + a_off;
#pragma unroll 2
        for (int ks = 0; ks < 8; ks++) {
            uint32_t ab[4], bU[10];
            LDSM4(ab[0], ab[1], ab[2], ab[3], wfb + ks * 32);
            load_B5(vT24 + ks * 32, vT22 + ks * 32, bU);
            mma5(accF, ab, bU);
        }
    }
#pragma unroll
    for (int t = 0; t < 5; t++) {
#pragma unroll
        for (int r = 0; r < 4; r++) {
            const int col = t * 8 + ecolp + (r & 1);
            const int o = o0 + erow + ((r >> 1) << 3);
            if (col >= 2 && col <= 33) {
                const int n = g0 - 2 + col;
                out[n * 128 + o] = fmaxf(accF[t][r], 0.f);
            }
        }
    }
}

// ---------------------------------------------------------------------------
extern "C" void kernel_launch(void* const* d_in, const int* in_sizes, int n_in,
                              void* d_out, int out_size)
{
    const float* x    = (const float*)d_in[0];
    const float* w1dw = (const float*)d_in[1];
    const float* w1pw = (const float*)d_in[2];
    const float* w21  = (const float*)d_in[3];
    const float* w2dw = (const float*)d_in[4];
    const float* w2pw = (const float*)d_in[5];
    const float* wf   = (const float*)d_in[6];
    float* out = (float*)d_out;

    prep_kernel<<<64, 256>>>(w1dw, w1pw, w21, w2dw, w2pw, wf);

    cudaFuncSetAttribute(fused_kernel, cudaFuncAttributeMaxDynamicSharedMemorySize, SM_TOTAL);
    fused_kernel<<<NPOS / TN, NT, SM_TOTAL>>>(x, out);
}